// round 2
// baseline (speedup 1.0000x reference)
#include <cuda_runtime.h>
#include <cstdint>

#define NPTS 500000
#define NSEG 80000          // 2 * 40000 clusters (fg/bg)
#define SEGW 92             // 91 features + count
#define DIN 182
#define NTILES 3907

__device__ __align__(16) float g_seg[NSEG * SEGW];   // ~29.4 MB scratch
__device__ float g_sum[128], g_sumsq[128], g_scale[128], g_shift[128];
__device__ int g_flags;

// ---- f32x2 packed helpers (FFMA2) ----
__device__ __forceinline__ unsigned long long pk2(float a) {
    unsigned long long r; asm("mov.b64 %0,{%1,%1};" : "=l"(r) : "f"(a)); return r;
}
__device__ __forceinline__ void upk(unsigned long long v, float& a, float& b) {
    asm("mov.b64 {%0,%1},%2;" : "=f"(a), "=f"(b) : "l"(v));
}
__device__ __forceinline__ void fma2(unsigned long long& d, unsigned long long a, unsigned long long b) {
    asm("fma.rn.f32x2 %0,%1,%2,%0;" : "+l"(d) : "l"(a), "l"(b));
}

__device__ __forceinline__ int fg_of(const void* m, int p, int fl) {
    if (fl & 2) return ((const float*)m)[p] != 0.0f;   // float32
    if (fl & 1) return ((const unsigned char*)m)[p] != 0; // packed bool
    return ((const int*)m)[p] != 0;                    // int32
}

// K0: zero scratch
__global__ void k_zero() {
    int64_t i = (int64_t)blockIdx.x * blockDim.x + threadIdx.x;
    int64_t st = (int64_t)gridDim.x * blockDim.x;
    float4 z = make_float4(0.f, 0.f, 0.f, 0.f);
    for (int64_t j = i; j < (int64_t)NSEG * SEGW / 4; j += st) ((float4*)g_seg)[j] = z;
    if (i < 128) { g_sum[i] = 0.f; g_sumsq[i] = 0.f; }
    if (i == 0) g_flags = 0;
}

// K1: classify fg_mask storage (bool8 / int32 / float32)
__global__ void k_detect(const unsigned int* __restrict__ w) {
    int f = 0;
    for (int i = blockIdx.x * blockDim.x + threadIdx.x; i < 125000; i += gridDim.x * blockDim.x) {
        unsigned int x = w[i];
        if (x == 0x3f800000u) f |= 2;
        else if (x > 1u) f |= 1;
    }
    if (f) atomicOr(&g_flags, f);
}

// K2: scatter segment sums, one warp per point
__global__ void k_scatter(const float* __restrict__ pts, const float* __restrict__ proj,
                          const float* __restrict__ feat, const float* __restrict__ logi,
                          const int* __restrict__ cidx, const void* __restrict__ fgm) {
    const int fl = g_flags;
    const int lane = threadIdx.x & 31;
    const int gw = (blockIdx.x * blockDim.x + threadIdx.x) >> 5;
    const int nw = (gridDim.x * blockDim.x) >> 5;
    for (int p = gw; p < NPTS; p += nw) {
        int g = fg_of(fgm, p, fl);
        float* row = g_seg + (size_t)(cidx[p] * 2 + g) * SEGW;
        atomicAdd(row + lane,      feat[(size_t)p * 64 + lane]);
        atomicAdd(row + lane + 32, feat[(size_t)p * 64 + lane + 32]);
        int c = lane + 64;
        if (c < SEGW) {
            float v;
            if (c < 84)      v = logi[(size_t)p * 20 + c - 64];
            else if (c < 88) v = pts [(size_t)p * 4  + c - 84];
            else if (c < 91) v = proj[(size_t)p * 3  + c - 88];
            else             v = 1.0f;
            atomicAdd(row + c, v);
        }
    }
}

// K3: sums -> means
__global__ void k_means() {
    const int lane = threadIdx.x & 31;
    const int gw = (blockIdx.x * blockDim.x + threadIdx.x) >> 5;
    const int nw = (gridDim.x * blockDim.x) >> 5;
    for (int s = gw; s < NSEG; s += nw) {
        float* row = g_seg + (size_t)s * SEGW;
        float cnt = row[91];
        float inv = (cnt > 0.f) ? (1.0f / cnt) : 0.0f;
        for (int c = lane; c < 91; c += 32) row[c] *= inv;
    }
}

// K4: fused gather + GEMM (f32x2) + bias + batch-stat accumulation
__global__ __launch_bounds__(256) void k_gemm(
    const float* __restrict__ pts, const float* __restrict__ proj,
    const float* __restrict__ feat, const float* __restrict__ logi,
    const int* __restrict__ cidx, const void* __restrict__ fgm,
    const float* __restrict__ W, const float* __restrict__ bias,
    float* __restrict__ hout)
{
    __shared__ float xs[128 * 16];    // x tile chunk  [m][k]
    __shared__ float ws[16 * 128];    // W tile chunk  [k][n]
    __shared__ int   rs[128];
    __shared__ float bias_s[128], ssum_s[128], ssq_s[128];

    const int tid = threadIdx.x;
    const int tx = tid & 15, ty = tid >> 4;
    const int m = tid >> 1, kk0 = (tid & 1) * 8;
    const int base = blockIdx.x * 128;
    const int p = base + m;
    const int fl = g_flags;

    if (tid < 128) {
        bias_s[tid] = bias[tid];
        ssum_s[tid] = 0.f; ssq_s[tid] = 0.f;
        int q = base + tid;
        rs[tid] = (q < NPTS) ? (cidx[q] * 2 + fg_of(fgm, q, fl)) * SEGW : -1;
    }

    unsigned long long acc[32];
    #pragma unroll
    for (int i = 0; i < 32; i++) acc[i] = 0ull;

    #pragma unroll 1
    for (int kc = 0; kc < 192; kc += 16) {
        __syncthreads();
        #pragma unroll
        for (int i = 0; i < 8; i++) {     // W chunk (m doubles as n)
            int kg = kc + kk0 + i;
            ws[(kk0 + i) * 128 + m] = (kg < DIN) ? W[m * DIN + kg] : 0.f;
        }
        #pragma unroll
        for (int i = 0; i < 8; i++) {     // x chunk
            int kg = kc + kk0 + i;
            float v = 0.f;
            if (p < NPTS && kg < DIN) {
                if (kg < 64)      v = feat[(size_t)p * 64 + kg];
                else if (kg < 84) v = logi[(size_t)p * 20 + kg - 64];
                else if (kg < 88) v = pts [(size_t)p * 4  + kg - 84];
                else if (kg < 91) v = proj[(size_t)p * 3  + kg - 88];
                else { int r = rs[m]; if (r >= 0) v = g_seg[(size_t)r + kg - 91]; }
            }
            xs[m * 16 + kk0 + i] = v;
        }
        __syncthreads();
        #pragma unroll
        for (int k = 0; k < 16; k++) {
            unsigned long long b4[4];
            #pragma unroll
            for (int j = 0; j < 4; j++)
                b4[j] = *(const unsigned long long*)(ws + k * 128 + tx * 8 + j * 2);
            #pragma unroll
            for (int i = 0; i < 8; i++) {
                unsigned long long a2 = pk2(xs[(ty * 8 + i) * 16 + k]);
                #pragma unroll
                for (int j = 0; j < 4; j++) fma2(acc[i * 4 + j], a2, b4[j]);
            }
        }
    }

    // epilogue: bias, store h, column sums
    float csum[8], csq[8];
    #pragma unroll
    for (int j = 0; j < 8; j++) { csum[j] = 0.f; csq[j] = 0.f; }
    #pragma unroll
    for (int i = 0; i < 8; i++) {
        float c[8];
        #pragma unroll
        for (int j = 0; j < 4; j++) upk(acc[i * 4 + j], c[2 * j], c[2 * j + 1]);
        int row = base + ty * 8 + i;
        if (row < NPTS) {
            #pragma unroll
            for (int j = 0; j < 8; j++) {
                c[j] += bias_s[tx * 8 + j];
                csum[j] += c[j]; csq[j] += c[j] * c[j];
            }
            float4* o = (float4*)(hout + (size_t)row * 128 + tx * 8);
            o[0] = make_float4(c[0], c[1], c[2], c[3]);
            o[1] = make_float4(c[4], c[5], c[6], c[7]);
        }
    }
    #pragma unroll
    for (int j = 0; j < 8; j++) {
        atomicAdd(&ssum_s[tx * 8 + j], csum[j]);
        atomicAdd(&ssq_s [tx * 8 + j], csq[j]);
    }
    __syncthreads();
    if (tid < 128) {
        atomicAdd(&g_sum[tid],   ssum_s[tid]);
        atomicAdd(&g_sumsq[tid], ssq_s[tid]);
    }
}

// K5: BN coefficients
__global__ void k_bn(const float* __restrict__ gamma, const float* __restrict__ beta) {
    int c = threadIdx.x;
    float mu = g_sum[c] * (1.0f / NPTS);
    float var = g_sumsq[c] * (1.0f / NPTS) - mu * mu;
    float sc = gamma[c] * rsqrtf(var + 1e-5f);
    g_scale[c] = sc;
    g_shift[c] = beta[c] - mu * sc;
}

// K6: normalize + LeakyReLU, in place
__global__ void k_apply(float* __restrict__ out) {
    int64_t i0 = (int64_t)blockIdx.x * blockDim.x + threadIdx.x;
    int64_t st = (int64_t)gridDim.x * blockDim.x;
    float4* o4 = (float4*)out;
    const int64_t n4 = (int64_t)NPTS * 32;
    for (int64_t i = i0; i < n4; i += st) {
        float4 v = o4[i];
        int c = (int)(i & 31) * 4;
        float a0 = v.x * g_scale[c]     + g_shift[c];
        float a1 = v.y * g_scale[c + 1] + g_shift[c + 1];
        float a2 = v.z * g_scale[c + 2] + g_shift[c + 2];
        float a3 = v.w * g_scale[c + 3] + g_shift[c + 3];
        v.x = a0 >= 0.f ? a0 : 0.1f * a0;
        v.y = a1 >= 0.f ? a1 : 0.1f * a1;
        v.z = a2 >= 0.f ? a2 : 0.1f * a2;
        v.w = a3 >= 0.f ? a3 : 0.1f * a3;
        o4[i] = v;
    }
}

extern "C" void kernel_launch(void* const* d_in, const int* in_sizes, int n_in,
                              void* d_out, int out_size) {
    const float* pts  = (const float*)d_in[0];
    const float* proj = (const float*)d_in[1];
    const float* feat = (const float*)d_in[2];
    const float* logi = (const float*)d_in[3];
    const int*   cidx = (const int*)d_in[4];
    const void*  fgm  = d_in[5];
    const float* W    = (const float*)d_in[6];
    const float* b    = (const float*)d_in[7];
    const float* gamma= (const float*)d_in[8];
    const float* beta = (const float*)d_in[9];
    float* out = (float*)d_out;

    k_zero<<<2048, 256>>>();
    k_detect<<<64, 256>>>((const unsigned int*)fgm);
    k_scatter<<<2048, 256>>>(pts, proj, feat, logi, cidx, fgm);
    k_means<<<640, 256>>>();
    k_gemm<<<NTILES, 256>>>(pts, proj, feat, logi, cidx, fgm, W, b, out);
    k_bn<<<1, 128>>>(gamma, beta);
    k_apply<<<2048, 256>>>(out);
}

// round 6
// speedup vs baseline: 1.7922x; 1.7922x over previous
#include <cuda_runtime.h>
#include <cstdint>

#define NPTS 500000
#define NSEG 80000
#define SEGW 92
#define DIN 182
#define NTILES 3907
#define GEMM_GRID 148

__device__ __align__(16) float g_seg[NSEG * SEGW];   // sums + count (col 91), ~29.4MB
__device__ float g_sum[128], g_sumsq[128], g_scale[128], g_shift[128];
__device__ int g_flags;

// ---- f32x2 packed helpers ----
__device__ __forceinline__ unsigned long long pk2(float a) {
    unsigned long long r; asm("mov.b64 %0,{%1,%1};" : "=l"(r) : "f"(a)); return r;
}
__device__ __forceinline__ void upk(unsigned long long v, float& a, float& b) {
    asm("mov.b64 {%0,%1},%2;" : "=f"(a), "=f"(b) : "l"(v));
}
__device__ __forceinline__ void fma2(unsigned long long& d, unsigned long long a, unsigned long long b) {
    asm("fma.rn.f32x2 %0,%1,%2,%0;" : "+l"(d) : "l"(a), "l"(b));
}
__device__ __forceinline__ int fg_of(const void* m, int p, int fl) {
    if (fl & 2) return ((const float*)m)[p] != 0.0f;
    if (fl & 1) return ((const unsigned char*)m)[p] != 0;
    return ((const int*)m)[p] != 0;
}

// ---------------- K0: zero scratch ----------------
__global__ void k_zero() {
    int64_t i = (int64_t)blockIdx.x * blockDim.x + threadIdx.x;
    int64_t st = (int64_t)gridDim.x * blockDim.x;
    float4 z = make_float4(0.f, 0.f, 0.f, 0.f);
    for (int64_t j = i; j < (int64_t)NSEG * SEGW / 4; j += st) ((float4*)g_seg)[j] = z;
    if (i < 128) { g_sum[i] = 0.f; g_sumsq[i] = 0.f; }
    if (i == 0) g_flags = 0;
}

// ---------------- K1: detect fg_mask dtype ----------------
__global__ void k_detect(const unsigned int* __restrict__ w) {
    int f = 0;
    for (int i = blockIdx.x * blockDim.x + threadIdx.x; i < 125000; i += gridDim.x * blockDim.x) {
        unsigned int x = w[i];
        if (x == 0x3f800000u) f |= 2;
        else if (x > 1u) f |= 1;
    }
    if (f) atomicOr(&g_flags, f);
}

// ---------------- K2: scatter segment sums (warp/point, v4 red) ----------------
__global__ void k_scatter(const float* __restrict__ pts, const float* __restrict__ proj,
                          const float* __restrict__ feat, const float* __restrict__ logi,
                          const int* __restrict__ cidx, const void* __restrict__ fgm) {
    const int fl = g_flags;
    const int lane = threadIdx.x & 31;
    const int gw = (blockIdx.x * blockDim.x + threadIdx.x) >> 5;
    const int nw = (gridDim.x * blockDim.x) >> 5;
    for (int p = gw; p < NPTS; p += nw) {
        int ci = 0, g = 0;
        if (lane == 0) { ci = cidx[p]; g = fg_of(fgm, p, fl); }
        ci = __shfl_sync(0xffffffffu, ci, 0);
        g  = __shfl_sync(0xffffffffu, g, 0);
        float* row = g_seg + (size_t)(ci * 2 + g) * SEGW;
        if (lane < 23) {
            float4 v;
            if (lane < 16)       v = *(const float4*)(feat + (size_t)p * 64 + lane * 4);
            else if (lane < 21)  v = *(const float4*)(logi + (size_t)p * 20 + (lane - 16) * 4);
            else if (lane == 21) v = *(const float4*)(pts + (size_t)p * 4);
            else {
                const float* pr = proj + (size_t)p * 3;
                v = make_float4(pr[0], pr[1], pr[2], 1.0f);
            }
            asm volatile("red.global.add.v4.f32 [%0],{%1,%2,%3,%4};"
                         :: "l"(row + lane * 4), "f"(v.x), "f"(v.y), "f"(v.z), "f"(v.w) : "memory");
        }
    }
}

// ---------------- K3: persistent fused gather + FFMA2 GEMM + bias + stats ----------------
// smem: ws[192*128] | xs[192*128] | bias[128] | red[256]   = 198144 bytes
#define SMEM_GEMM ((24576 + 24576 + 128 + 256) * 4)

__global__ __launch_bounds__(256, 1) void k_gemm(
    const float* __restrict__ pts, const float* __restrict__ proj,
    const float* __restrict__ feat, const float* __restrict__ logi,
    const int* __restrict__ cidx, const void* __restrict__ fgm,
    const float* __restrict__ W, const float* __restrict__ bias,
    float* __restrict__ hout)
{
    extern __shared__ __align__(16) float smf[];
    float* ws = smf;                 // [k][n] 192x128
    float* xs = smf + 24576;         // [k][m] 192x128
    float* bias_s = smf + 49152;     // 128
    float* red = smf + 49280;        // 256

    const int tid = threadIdx.x;
    const int tx = tid & 15, ty = tid >> 4;       // n-group, m-group
    const int m = tid >> 1, half = tid & 1;       // gather mapping
    const int fl = g_flags;

    // stage W transposed (k-major), once
    for (int i = tid; i < 24576; i += 256) {
        int k = i >> 7, n = i & 127;
        ws[i] = (k < DIN) ? W[n * DIN + k] : 0.f;
    }
    if (tid < 128) bias_s[tid] = bias[tid];

    float s_sum[8], s_sq[8];
    #pragma unroll
    for (int j = 0; j < 8; j++) { s_sum[j] = 0.f; s_sq[j] = 0.f; }

    __syncthreads();

    for (int t = blockIdx.x; t < NTILES; t += GEMM_GRID) {
        const int base = t * 128;
        const int p = base + m;
        const bool ok = p < NPTS;

        const float* srow = g_seg;
        float inv = 0.f;
        if (ok) {
            int r = (cidx[p] * 2 + fg_of(fgm, p, fl)) * SEGW;
            srow = g_seg + r;
            float cnt = srow[91];
            inv = (cnt > 0.f) ? (1.0f / cnt) : 0.f;
        }

        // ---- gather into xs[k][m]; half 0 -> k 0..95, half 1 -> k 96..191 ----
        if (half == 0) {
            if (ok) {
                #pragma unroll
                for (int i = 0; i < 16; i++) {
                    float4 f = *(const float4*)(feat + (size_t)p * 64 + i * 4);
                    xs[(4 * i + 0) * 128 + m] = f.x; xs[(4 * i + 1) * 128 + m] = f.y;
                    xs[(4 * i + 2) * 128 + m] = f.z; xs[(4 * i + 3) * 128 + m] = f.w;
                }
                #pragma unroll
                for (int i = 0; i < 5; i++) {
                    float4 f = *(const float4*)(logi + (size_t)p * 20 + i * 4);
                    xs[(64 + 4 * i) * 128 + m] = f.x; xs[(65 + 4 * i) * 128 + m] = f.y;
                    xs[(66 + 4 * i) * 128 + m] = f.z; xs[(67 + 4 * i) * 128 + m] = f.w;
                }
                float4 f = *(const float4*)(pts + (size_t)p * 4);
                xs[84 * 128 + m] = f.x; xs[85 * 128 + m] = f.y;
                xs[86 * 128 + m] = f.z; xs[87 * 128 + m] = f.w;
                const float* pr = proj + (size_t)p * 3;
                xs[88 * 128 + m] = pr[0]; xs[89 * 128 + m] = pr[1]; xs[90 * 128 + m] = pr[2];
                float4 s = *(const float4*)(srow);
                xs[91 * 128 + m] = s.x * inv; xs[92 * 128 + m] = s.y * inv;
                xs[93 * 128 + m] = s.z * inv; xs[94 * 128 + m] = s.w * inv;
                xs[95 * 128 + m] = srow[4] * inv;
            } else {
                #pragma unroll
                for (int k = 0; k < 96; k++) xs[k * 128 + m] = 0.f;
            }
        } else {
            if (ok) {
                xs[96 * 128 + m] = srow[5] * inv;
                xs[97 * 128 + m] = srow[6] * inv;
                xs[98 * 128 + m] = srow[7] * inv;
                #pragma unroll
                for (int q = 0; q < 20; q++) {
                    float4 s = *(const float4*)(srow + 8 + 4 * q);
                    xs[(99 + 4 * q) * 128 + m]  = s.x * inv;
                    xs[(100 + 4 * q) * 128 + m] = s.y * inv;
                    xs[(101 + 4 * q) * 128 + m] = s.z * inv;
                    xs[(102 + 4 * q) * 128 + m] = s.w * inv;
                }
                xs[179 * 128 + m] = srow[88] * inv;
                xs[180 * 128 + m] = srow[89] * inv;
                xs[181 * 128 + m] = srow[90] * inv;
            } else {
                #pragma unroll
                for (int k = 96; k < 182; k++) xs[k * 128 + m] = 0.f;
            }
            #pragma unroll
            for (int k = 182; k < 192; k++) xs[k * 128 + m] = 0.f;
        }
        __syncthreads();

        // ---- compute: 8m x 8n per thread, f32x2 packed ----
        unsigned long long acc[32];
        #pragma unroll
        for (int i = 0; i < 32; i++) acc[i] = 0ull;

        #pragma unroll 1
        for (int k0 = 0; k0 < 192; k0 += 8) {
            #pragma unroll
            for (int kk = 0; kk < 8; kk++) {
                const int k = k0 + kk;
                const float* xr = xs + k * 128 + ty * 8;
                float4 a0 = *(const float4*)xr;
                float4 a1 = *(const float4*)(xr + 4);
                ulonglong2 b0 = *(const ulonglong2*)(ws + k * 128 + tx * 8);
                ulonglong2 b1 = *(const ulonglong2*)(ws + k * 128 + tx * 8 + 4);
                unsigned long long bb0 = b0.x, bb1 = b0.y, bb2 = b1.x, bb3 = b1.y;
                float av[8] = {a0.x, a0.y, a0.z, a0.w, a1.x, a1.y, a1.z, a1.w};
                #pragma unroll
                for (int i = 0; i < 8; i++) {
                    unsigned long long a2 = pk2(av[i]);
                    fma2(acc[i * 4 + 0], a2, bb0);
                    fma2(acc[i * 4 + 1], a2, bb1);
                    fma2(acc[i * 4 + 2], a2, bb2);
                    fma2(acc[i * 4 + 3], a2, bb3);
                }
            }
        }

        // ---- epilogue: bias, stats, store ----
        #pragma unroll
        for (int i = 0; i < 8; i++) {
            int row = base + ty * 8 + i;
            if (row < NPTS) {
                float c[8];
                #pragma unroll
                for (int j = 0; j < 4; j++) upk(acc[i * 4 + j], c[2 * j], c[2 * j + 1]);
                #pragma unroll
                for (int j = 0; j < 8; j++) {
                    c[j] += bias_s[tx * 8 + j];
                    s_sum[j] += c[j];
                    s_sq[j] += c[j] * c[j];
                }
                float* o = hout + (size_t)row * 128 + tx * 8;
                *(float4*)o       = make_float4(c[0], c[1], c[2], c[3]);
                *(float4*)(o + 4) = make_float4(c[4], c[5], c[6], c[7]);
            }
        }
        __syncthreads();
    }

    // ---- per-CTA stats reduction ----
    if (tid < 256) red[tid] = 0.f;
    __syncthreads();
    #pragma unroll
    for (int j = 0; j < 8; j++) {
        atomicAdd(&red[tx * 8 + j], s_sum[j]);
        atomicAdd(&red[128 + tx * 8 + j], s_sq[j]);
    }
    __syncthreads();
    if (tid < 128) {
        atomicAdd(&g_sum[tid], red[tid]);
        atomicAdd(&g_sumsq[tid], red[128 + tid]);
    }
}

// ---------------- K4: BN coefficients ----------------
__global__ void k_bn(const float* __restrict__ gamma, const float* __restrict__ beta) {
    int c = threadIdx.x;
    float mu = g_sum[c] * (1.0f / NPTS);
    float var = g_sumsq[c] * (1.0f / NPTS) - mu * mu;
    float sc = gamma[c] * rsqrtf(var + 1e-5f);
    g_scale[c] = sc;
    g_shift[c] = beta[c] - mu * sc;
}

// ---------------- K5: normalize + LeakyReLU ----------------
__global__ void k_apply(float* __restrict__ out) {
    int64_t i0 = (int64_t)blockIdx.x * blockDim.x + threadIdx.x;
    int64_t st = (int64_t)gridDim.x * blockDim.x;
    float4* o4 = (float4*)out;
    for (int64_t i = i0; i < (int64_t)NPTS * 32; i += st) {
        float4 v = o4[i];
        int c = (int)(i & 31) * 4;
        float a0 = v.x * g_scale[c]     + g_shift[c];
        float a1 = v.y * g_scale[c + 1] + g_shift[c + 1];
        float a2 = v.z * g_scale[c + 2] + g_shift[c + 2];
        float a3 = v.w * g_scale[c + 3] + g_shift[c + 3];
        v.x = a0 >= 0.f ? a0 : 0.1f * a0;
        v.y = a1 >= 0.f ? a1 : 0.1f * a1;
        v.z = a2 >= 0.f ? a2 : 0.1f * a2;
        v.w = a3 >= 0.f ? a3 : 0.1f * a3;
        o4[i] = v;
    }
}

extern "C" void kernel_launch(void* const* d_in, const int* in_sizes, int n_in,
                              void* d_out, int out_size) {
    const float* pts  = (const float*)d_in[0];
    const float* proj = (const float*)d_in[1];
    const float* feat = (const float*)d_in[2];
    const float* logi = (const float*)d_in[3];
    const int*   cidx = (const int*)d_in[4];
    const void*  fgm  = d_in[5];
    const float* W    = (const float*)d_in[6];
    const float* b    = (const float*)d_in[7];
    const float* gamma= (const float*)d_in[8];
    const float* beta = (const float*)d_in[9];
    float* out = (float*)d_out;

    cudaFuncSetAttribute(k_gemm, cudaFuncAttributeMaxDynamicSharedMemorySize, SMEM_GEMM);

    k_zero<<<2048, 256>>>();
    k_detect<<<64, 256>>>((const unsigned int*)fgm);
    k_scatter<<<2048, 256>>>(pts, proj, feat, logi, cidx, fgm);
    k_gemm<<<GEMM_GRID, 256, SMEM_GEMM>>>(pts, proj, feat, logi, cidx, fgm, W, b, out);
    k_bn<<<1, 128>>>(gamma, beta);
    k_apply<<<2048, 256>>>(out);
}

// round 7
// speedup vs baseline: 1.9914x; 1.1112x over previous
#include <cuda_runtime.h>
#include <cstdint>

#define NPTS 500000
#define NSEG 80000
#define SEGW 92
#define DIN 182
#define NTILES 3907
#define GEMM_GRID 148

__device__ __align__(16) float g_seg[NSEG * SEGW];   // sums + count (col 91), ~29.4MB
__device__ float g_sum[128], g_sumsq[128], g_scale[128], g_shift[128];
__device__ int g_flags;

// ---- f32x2 packed helpers ----
__device__ __forceinline__ unsigned long long pk2(float a) {
    unsigned long long r; asm("mov.b64 %0,{%1,%1};" : "=l"(r) : "f"(a)); return r;
}
__device__ __forceinline__ void upk(unsigned long long v, float& a, float& b) {
    asm("mov.b64 {%0,%1},%2;" : "=f"(a), "=f"(b) : "l"(v));
}
__device__ __forceinline__ void fma2(unsigned long long& d, unsigned long long a, unsigned long long b) {
    asm("fma.rn.f32x2 %0,%1,%2,%0;" : "+l"(d) : "l"(a), "l"(b));
}
__device__ __forceinline__ int fg_of(const void* m, int p, int fl) {
    if (fl & 2) return ((const float*)m)[p] != 0.0f;
    if (fl & 1) return ((const unsigned char*)m)[p] != 0;
    return ((const int*)m)[p] != 0;
}

// ---------------- K0: zero scratch ----------------
__global__ void k_zero() {
    int64_t i = (int64_t)blockIdx.x * blockDim.x + threadIdx.x;
    int64_t st = (int64_t)gridDim.x * blockDim.x;
    float4 z = make_float4(0.f, 0.f, 0.f, 0.f);
    for (int64_t j = i; j < (int64_t)NSEG * SEGW / 4; j += st) ((float4*)g_seg)[j] = z;
    if (i < 128) { g_sum[i] = 0.f; g_sumsq[i] = 0.f; }
    if (i == 0) g_flags = 0;
}

// ---------------- K1: detect fg_mask dtype ----------------
__global__ void k_detect(const unsigned int* __restrict__ w) {
    int f = 0;
    for (int i = blockIdx.x * blockDim.x + threadIdx.x; i < 125000; i += gridDim.x * blockDim.x) {
        unsigned int x = w[i];
        if (x == 0x3f800000u) f |= 2;
        else if (x > 1u) f |= 1;
    }
    if (f) atomicOr(&g_flags, f);
}

// ---------------- K2: scatter segment sums (warp/point, v4 red) ----------------
__global__ void k_scatter(const float* __restrict__ pts, const float* __restrict__ proj,
                          const float* __restrict__ feat, const float* __restrict__ logi,
                          const int* __restrict__ cidx, const void* __restrict__ fgm) {
    const int fl = g_flags;
    const int lane = threadIdx.x & 31;
    const int gw = (blockIdx.x * blockDim.x + threadIdx.x) >> 5;
    const int nw = (gridDim.x * blockDim.x) >> 5;
    for (int p = gw; p < NPTS; p += nw) {
        int ci = 0, g = 0;
        if (lane == 0) { ci = cidx[p]; g = fg_of(fgm, p, fl); }
        ci = __shfl_sync(0xffffffffu, ci, 0);
        g  = __shfl_sync(0xffffffffu, g, 0);
        float* row = g_seg + (size_t)(ci * 2 + g) * SEGW;
        if (lane < 23) {
            float4 v;
            if (lane < 16)       v = *(const float4*)(feat + (size_t)p * 64 + lane * 4);
            else if (lane < 21)  v = *(const float4*)(logi + (size_t)p * 20 + (lane - 16) * 4);
            else if (lane == 21) v = *(const float4*)(pts + (size_t)p * 4);
            else {
                const float* pr = proj + (size_t)p * 3;
                v = make_float4(pr[0], pr[1], pr[2], 1.0f);
            }
            asm volatile("red.global.add.v4.f32 [%0],{%1,%2,%3,%4};"
                         :: "l"(row + lane * 4), "f"(v.x), "f"(v.y), "f"(v.z), "f"(v.w) : "memory");
        }
    }
}

// ---------------- K3: persistent fused gather + FFMA2 GEMM + bias + stats ----------------
// smem: ws[192*128] | xs[192*128] | bias[128] | red[256]  = 198656 bytes
#define SMEM_GEMM ((24576 + 24576 + 128 + 256) * 4)

__global__ __launch_bounds__(512, 1) void k_gemm(
    const float* __restrict__ pts, const float* __restrict__ proj,
    const float* __restrict__ feat, const float* __restrict__ logi,
    const int* __restrict__ cidx, const void* __restrict__ fgm,
    const float* __restrict__ W, const float* __restrict__ bias,
    float* __restrict__ hout)
{
    extern __shared__ __align__(16) float smf[];
    float* ws = smf;                 // [k][n] 192x128
    float* xs = smf + 24576;         // [k][m] 192x128
    float* bias_s = smf + 49152;     // 128
    float* red = smf + 49280;        // 256

    const int tid = threadIdx.x;
    const int tx = tid & 31, ty = tid >> 5;       // compute: n-group(4), m-group(8)
    const int gm = tid & 127, gq = tid >> 7;      // gather: row, K-quarter
    const int fl = g_flags;

    // stage W k-major, once per CTA
    for (int i = tid; i < 24576; i += 512) {
        int k = i >> 7, n = i & 127;
        ws[i] = (k < DIN) ? W[n * DIN + k] : 0.f;
    }
    if (tid < 128) bias_s[tid] = bias[tid];

    float s_sum[4], s_sq[4];
    #pragma unroll
    for (int j = 0; j < 4; j++) { s_sum[j] = 0.f; s_sq[j] = 0.f; }

    __syncthreads();

    for (int t = blockIdx.x; t < NTILES; t += GEMM_GRID) {
        const int base = t * 128;
        const int p = base + gm;
        const bool ok = p < NPTS;
        float* xc = xs + gm;                      // write column for this row

        // ---- gather into xs[k][m]; quarter gq covers k in [48*gq, 48*gq+48) ----
        if (gq == 0) {
            if (ok) {
                #pragma unroll
                for (int i = 0; i < 12; i++) {
                    float4 f = *(const float4*)(feat + (size_t)p * 64 + i * 4);
                    xc[(4 * i + 0) * 128] = f.x; xc[(4 * i + 1) * 128] = f.y;
                    xc[(4 * i + 2) * 128] = f.z; xc[(4 * i + 3) * 128] = f.w;
                }
            } else {
                #pragma unroll
                for (int k = 0; k < 48; k++) xc[k * 128] = 0.f;
            }
        } else {
            const float* srow = g_seg;
            float inv = 0.f;
            if (ok) {
                int r = (cidx[p] * 2 + fg_of(fgm, p, fl)) * SEGW;
                srow = g_seg + r;
                float cnt = srow[91];
                inv = (cnt > 0.f) ? (1.0f / cnt) : 0.f;
            }
            if (gq == 1) {
                if (ok) {
                    #pragma unroll
                    for (int i = 0; i < 4; i++) {
                        float4 f = *(const float4*)(feat + (size_t)p * 64 + 48 + i * 4);
                        xc[(48 + 4 * i) * 128] = f.x; xc[(49 + 4 * i) * 128] = f.y;
                        xc[(50 + 4 * i) * 128] = f.z; xc[(51 + 4 * i) * 128] = f.w;
                    }
                    #pragma unroll
                    for (int i = 0; i < 5; i++) {
                        float4 f = *(const float4*)(logi + (size_t)p * 20 + i * 4);
                        xc[(64 + 4 * i) * 128] = f.x; xc[(65 + 4 * i) * 128] = f.y;
                        xc[(66 + 4 * i) * 128] = f.z; xc[(67 + 4 * i) * 128] = f.w;
                    }
                    float4 f = *(const float4*)(pts + (size_t)p * 4);
                    xc[84 * 128] = f.x; xc[85 * 128] = f.y; xc[86 * 128] = f.z; xc[87 * 128] = f.w;
                    const float* pr = proj + (size_t)p * 3;
                    xc[88 * 128] = pr[0]; xc[89 * 128] = pr[1]; xc[90 * 128] = pr[2];
                    float4 s = *(const float4*)(srow);
                    xc[91 * 128] = s.x * inv; xc[92 * 128] = s.y * inv;
                    xc[93 * 128] = s.z * inv; xc[94 * 128] = s.w * inv;
                    xc[95 * 128] = srow[4] * inv;
                } else {
                    #pragma unroll
                    for (int k = 48; k < 96; k++) xc[k * 128] = 0.f;
                }
            } else if (gq == 2) {
                if (ok) {
                    xc[96 * 128] = srow[5] * inv;
                    xc[97 * 128] = srow[6] * inv;
                    xc[98 * 128] = srow[7] * inv;
                    #pragma unroll
                    for (int q = 0; q < 11; q++) {
                        float4 s = *(const float4*)(srow + 8 + 4 * q);
                        xc[(99 + 4 * q) * 128]  = s.x * inv;
                        xc[(100 + 4 * q) * 128] = s.y * inv;
                        xc[(101 + 4 * q) * 128] = s.z * inv;
                        xc[(102 + 4 * q) * 128] = s.w * inv;
                    }
                    xc[143 * 128] = srow[52] * inv;
                } else {
                    #pragma unroll
                    for (int k = 96; k < 144; k++) xc[k * 128] = 0.f;
                }
            } else {
                if (ok) {
                    xc[144 * 128] = srow[53] * inv;
                    xc[145 * 128] = srow[54] * inv;
                    xc[146 * 128] = srow[55] * inv;
                    #pragma unroll
                    for (int q = 0; q < 8; q++) {
                        float4 s = *(const float4*)(srow + 56 + 4 * q);
                        xc[(147 + 4 * q) * 128] = s.x * inv;
                        xc[(148 + 4 * q) * 128] = s.y * inv;
                        xc[(149 + 4 * q) * 128] = s.z * inv;
                        xc[(150 + 4 * q) * 128] = s.w * inv;
                    }
                    xc[179 * 128] = srow[88] * inv;
                    xc[180 * 128] = srow[89] * inv;
                    xc[181 * 128] = srow[90] * inv;
                } else {
                    #pragma unroll
                    for (int k = 144; k < 182; k++) xc[k * 128] = 0.f;
                }
                #pragma unroll
                for (int k = 182; k < 192; k++) xc[k * 128] = 0.f;
            }
        }
        __syncthreads();

        // ---- compute: 8m x 4n per thread; A packed along m (no pk2 on A) ----
        unsigned long long acc[16];
        #pragma unroll
        for (int i = 0; i < 16; i++) acc[i] = 0ull;

        #pragma unroll 1
        for (int k0 = 0; k0 < 192; k0 += 16) {
            #pragma unroll
            for (int kk = 0; kk < 16; kk++) {
                const int k = k0 + kk;
                ulonglong2 a01 = *(const ulonglong2*)(xs + k * 128 + ty * 8);
                ulonglong2 a23 = *(const ulonglong2*)(xs + k * 128 + ty * 8 + 4);
                float4 b = *(const float4*)(ws + k * 128 + tx * 4);
                unsigned long long b0 = pk2(b.x), b1 = pk2(b.y), b2 = pk2(b.z), b3 = pk2(b.w);
                fma2(acc[0],  a01.x, b0); fma2(acc[1],  a01.y, b0);
                fma2(acc[2],  a23.x, b0); fma2(acc[3],  a23.y, b0);
                fma2(acc[4],  a01.x, b1); fma2(acc[5],  a01.y, b1);
                fma2(acc[6],  a23.x, b1); fma2(acc[7],  a23.y, b1);
                fma2(acc[8],  a01.x, b2); fma2(acc[9],  a01.y, b2);
                fma2(acc[10], a23.x, b2); fma2(acc[11], a23.y, b2);
                fma2(acc[12], a01.x, b3); fma2(acc[13], a01.y, b3);
                fma2(acc[14], a23.x, b3); fma2(acc[15], a23.y, b3);
            }
        }

        // ---- epilogue: bias, stats, store (2 rows per m-pair) ----
        const float bj0 = bias_s[tx * 4], bj1 = bias_s[tx * 4 + 1];
        const float bj2 = bias_s[tx * 4 + 2], bj3 = bias_s[tx * 4 + 3];
        #pragma unroll
        for (int i = 0; i < 4; i++) {
            int r0 = base + ty * 8 + 2 * i;
            float c0[4], c1[4];
            upk(acc[i],      c0[0], c1[0]);
            upk(acc[4 + i],  c0[1], c1[1]);
            upk(acc[8 + i],  c0[2], c1[2]);
            upk(acc[12 + i], c0[3], c1[3]);
            c0[0] += bj0; c0[1] += bj1; c0[2] += bj2; c0[3] += bj3;
            c1[0] += bj0; c1[1] += bj1; c1[2] += bj2; c1[3] += bj3;
            if (r0 < NPTS) {
                #pragma unroll
                for (int j = 0; j < 4; j++) { s_sum[j] += c0[j]; s_sq[j] += c0[j] * c0[j]; }
                *(float4*)(hout + (size_t)r0 * 128 + tx * 4) = make_float4(c0[0], c0[1], c0[2], c0[3]);
                if (r0 + 1 < NPTS) {
                    #pragma unroll
                    for (int j = 0; j < 4; j++) { s_sum[j] += c1[j]; s_sq[j] += c1[j] * c1[j]; }
                    *(float4*)(hout + (size_t)(r0 + 1) * 128 + tx * 4) = make_float4(c1[0], c1[1], c1[2], c1[3]);
                }
            }
        }
        __syncthreads();
    }

    // ---- per-CTA stats reduction ----
    if (tid < 256) red[tid] = 0.f;
    __syncthreads();
    #pragma unroll
    for (int j = 0; j < 4; j++) {
        atomicAdd(&red[tx * 4 + j], s_sum[j]);
        atomicAdd(&red[128 + tx * 4 + j], s_sq[j]);
    }
    __syncthreads();
    if (tid < 128) {
        atomicAdd(&g_sum[tid], red[tid]);
        atomicAdd(&g_sumsq[tid], red[128 + tid]);
    }
}

// ---------------- K4: BN coefficients ----------------
__global__ void k_bn(const float* __restrict__ gamma, const float* __restrict__ beta) {
    int c = threadIdx.x;
    float mu = g_sum[c] * (1.0f / NPTS);
    float var = g_sumsq[c] * (1.0f / NPTS) - mu * mu;
    float sc = gamma[c] * rsqrtf(var + 1e-5f);
    g_scale[c] = sc;
    g_shift[c] = beta[c] - mu * sc;
}

// ---------------- K5: normalize + LeakyReLU ----------------
__global__ void k_apply(float* __restrict__ out) {
    int64_t i0 = (int64_t)blockIdx.x * blockDim.x + threadIdx.x;
    int64_t st = (int64_t)gridDim.x * blockDim.x;
    float4* o4 = (float4*)out;
    for (int64_t i = i0; i < (int64_t)NPTS * 32; i += st) {
        float4 v = o4[i];
        int c = (int)(i & 31) * 4;
        float a0 = v.x * g_scale[c]     + g_shift[c];
        float a1 = v.y * g_scale[c + 1] + g_shift[c + 1];
        float a2 = v.z * g_scale[c + 2] + g_shift[c + 2];
        float a3 = v.w * g_scale[c + 3] + g_shift[c + 3];
        v.x = a0 >= 0.f ? a0 : 0.1f * a0;
        v.y = a1 >= 0.f ? a1 : 0.1f * a1;
        v.z = a2 >= 0.f ? a2 : 0.1f * a2;
        v.w = a3 >= 0.f ? a3 : 0.1f * a3;
        o4[i] = v;
    }
}

extern "C" void kernel_launch(void* const* d_in, const int* in_sizes, int n_in,
                              void* d_out, int out_size) {
    const float* pts  = (const float*)d_in[0];
    const float* proj = (const float*)d_in[1];
    const float* feat = (const float*)d_in[2];
    const float* logi = (const float*)d_in[3];
    const int*   cidx = (const int*)d_in[4];
    const void*  fgm  = d_in[5];
    const float* W    = (const float*)d_in[6];
    const float* b    = (const float*)d_in[7];
    const float* gamma= (const float*)d_in[8];
    const float* beta = (const float*)d_in[9];
    float* out = (float*)d_out;

    cudaFuncSetAttribute(k_gemm, cudaFuncAttributeMaxDynamicSharedMemorySize, SMEM_GEMM);

    k_zero<<<2048, 256>>>();
    k_detect<<<64, 256>>>((const unsigned int*)fgm);
    k_scatter<<<2048, 256>>>(pts, proj, feat, logi, cidx, fgm);
    k_gemm<<<GEMM_GRID, 512, SMEM_GEMM>>>(pts, proj, feat, logi, cidx, fgm, W, b, out);
    k_bn<<<1, 128>>>(gamma, beta);
    k_apply<<<2048, 256>>>(out);
}

// round 8
// speedup vs baseline: 2.5076x; 1.2592x over previous
#include <cuda_runtime.h>
#include <cstdint>

#define NPTS 500000
#define NSEG 80000
#define SEGW 92
#define DIN 182
#define NT_B 3907      // ceil(500000/128)
#define NT_A 625       // 80000/128
#define GRID 296       // 2 CTAs/SM * 148

__device__ __align__(16) float g_seg[NSEG * SEGW];   // segment sums + count (col 91)
__device__ __align__(16) float g_Y[(size_t)NSEG * 128]; // W2*mean + bias per segment (41MB)
__device__ float g_sum[128], g_sumsq[128], g_scale[128], g_shift[128];
__device__ int g_flags;

// ---- f32x2 packed helpers ----
__device__ __forceinline__ unsigned long long pk2(float a) {
    unsigned long long r; asm("mov.b64 %0,{%1,%1};" : "=l"(r) : "f"(a)); return r;
}
__device__ __forceinline__ void upk(unsigned long long v, float& a, float& b) {
    asm("mov.b64 {%0,%1},%2;" : "=f"(a), "=f"(b) : "l"(v));
}
__device__ __forceinline__ void fma2(unsigned long long& d, unsigned long long a, unsigned long long b) {
    asm("fma.rn.f32x2 %0,%1,%2,%0;" : "+l"(d) : "l"(a), "l"(b));
}
__device__ __forceinline__ int fg_of(const void* m, int p, int fl) {
    if (fl & 2) return ((const float*)m)[p] != 0.0f;
    if (fl & 1) return ((const unsigned char*)m)[p] != 0;
    return ((const int*)m)[p] != 0;
}

// ---------------- K0: zero scratch ----------------
__global__ void k_zero() {
    int64_t i = (int64_t)blockIdx.x * blockDim.x + threadIdx.x;
    int64_t st = (int64_t)gridDim.x * blockDim.x;
    float4 z = make_float4(0.f, 0.f, 0.f, 0.f);
    for (int64_t j = i; j < (int64_t)NSEG * SEGW / 4; j += st) ((float4*)g_seg)[j] = z;
    if (i < 128) { g_sum[i] = 0.f; g_sumsq[i] = 0.f; }
    if (i == 0) g_flags = 0;
}

// ---------------- K1: detect fg_mask dtype ----------------
__global__ void k_detect(const unsigned int* __restrict__ w) {
    int f = 0;
    for (int i = blockIdx.x * blockDim.x + threadIdx.x; i < 125000; i += gridDim.x * blockDim.x) {
        unsigned int x = w[i];
        if (x == 0x3f800000u) f |= 2;
        else if (x > 1u) f |= 1;
    }
    if (f) atomicOr(&g_flags, f);
}

// ---------------- K2: scatter segment sums (warp/point, v4 red) ----------------
__global__ void k_scatter(const float* __restrict__ pts, const float* __restrict__ proj,
                          const float* __restrict__ feat, const float* __restrict__ logi,
                          const int* __restrict__ cidx, const void* __restrict__ fgm) {
    const int fl = g_flags;
    const int lane = threadIdx.x & 31;
    const int gw = (blockIdx.x * blockDim.x + threadIdx.x) >> 5;
    const int nw = (gridDim.x * blockDim.x) >> 5;
    for (int p = gw; p < NPTS; p += nw) {
        int ci = 0, g = 0;
        if (lane == 0) { ci = cidx[p]; g = fg_of(fgm, p, fl); }
        ci = __shfl_sync(0xffffffffu, ci, 0);
        g  = __shfl_sync(0xffffffffu, g, 0);
        float* row = g_seg + (size_t)(ci * 2 + g) * SEGW;
        if (lane < 23) {
            float4 v;
            if (lane < 16)       v = *(const float4*)(feat + (size_t)p * 64 + lane * 4);
            else if (lane < 21)  v = *(const float4*)(logi + (size_t)p * 20 + (lane - 16) * 4);
            else if (lane == 21) v = *(const float4*)(pts + (size_t)p * 4);
            else {
                const float* pr = proj + (size_t)p * 3;
                v = make_float4(pr[0], pr[1], pr[2], 1.0f);
            }
            asm volatile("red.global.add.v4.f32 [%0],{%1,%2,%3,%4};"
                         :: "l"(row + lane * 4), "f"(v.x), "f"(v.y), "f"(v.z), "f"(v.w) : "memory");
        }
    }
}

// ======== shared FFMA2 inner block: 16m x 4n per thread, K=96 ========
// ws[k][n] 96x128, xs[k][m] 96x128
#define MMA_BODY(ws, xs, acc, tx, ty)                                        \
    _Pragma("unroll 8")                                                       \
    for (int k = 0; k < 96; k++) {                                            \
        const float* xr = (xs) + k * 128 + (ty) * 16;                         \
        ulonglong2 a0 = *(const ulonglong2*)xr;                               \
        ulonglong2 a1 = *(const ulonglong2*)(xr + 4);                         \
        ulonglong2 a2 = *(const ulonglong2*)(xr + 8);                         \
        ulonglong2 a3 = *(const ulonglong2*)(xr + 12);                        \
        float4 b = *(const float4*)((ws) + k * 128 + (tx) * 4);               \
        unsigned long long b0 = pk2(b.x), b1 = pk2(b.y),                      \
                           b2 = pk2(b.z), b3 = pk2(b.w);                      \
        fma2(acc[0], a0.x, b0);  fma2(acc[1], a0.y, b0);                      \
        fma2(acc[2], a1.x, b0);  fma2(acc[3], a1.y, b0);                      \
        fma2(acc[4], a2.x, b0);  fma2(acc[5], a2.y, b0);                      \
        fma2(acc[6], a3.x, b0);  fma2(acc[7], a3.y, b0);                      \
        fma2(acc[8], a0.x, b1);  fma2(acc[9], a0.y, b1);                      \
        fma2(acc[10], a1.x, b1); fma2(acc[11], a1.y, b1);                     \
        fma2(acc[12], a2.x, b1); fma2(acc[13], a2.y, b1);                     \
        fma2(acc[14], a3.x, b1); fma2(acc[15], a3.y, b1);                     \
        fma2(acc[16], a0.x, b2); fma2(acc[17], a0.y, b2);                     \
        fma2(acc[18], a1.x, b2); fma2(acc[19], a1.y, b2);                     \
        fma2(acc[20], a2.x, b2); fma2(acc[21], a2.y, b2);                     \
        fma2(acc[22], a3.x, b2); fma2(acc[23], a3.y, b2);                     \
        fma2(acc[24], a0.x, b3); fma2(acc[25], a0.y, b3);                     \
        fma2(acc[26], a1.x, b3); fma2(acc[27], a1.y, b3);                     \
        fma2(acc[28], a2.x, b3); fma2(acc[29], a2.y, b3);                     \
        fma2(acc[30], a3.x, b3); fma2(acc[31], a3.y, b3);                     \
    }

// ---------------- K3: pass A — Y[s] = W2 * mean[s] + bias ----------------
// smem: ws 12288 | xs 12288 | bias 128  = 98816 B
#define SMEM_A ((12288 + 12288 + 128) * 4)

__global__ __launch_bounds__(256, 2) void k_segmm(const float* __restrict__ W,
                                                  const float* __restrict__ bias) {
    extern __shared__ __align__(16) float smf[];
    float* ws = smf;
    float* xs = smf + 12288;
    float* bias_s = smf + 24576;

    const int tid = threadIdx.x;
    const int tx = tid & 31, ty = tid >> 5;
    const int r = tid & 127, half = tid >> 7;

    for (int i = tid; i < 12288; i += 256) {
        int k = i >> 7, n = i & 127;
        ws[i] = (k < 91) ? W[n * DIN + 91 + k] : 0.f;
    }
    if (tid < 128) bias_s[tid] = bias[tid];
    __syncthreads();

    for (int t = blockIdx.x; t < NT_A; t += GRID) {
        const int s = t * 128 + r;                       // 625*128 == NSEG exactly
        const float* row = g_seg + (size_t)s * SEGW;
        float cnt = row[91];
        float inv = (cnt > 0.f) ? (1.0f / cnt) : 0.f;
        float* xc = xs + r;
        if (half == 0) {
            #pragma unroll
            for (int q = 0; q < 12; q++) {
                float4 f = *(const float4*)(row + 4 * q);
                xc[(4 * q + 0) * 128] = f.x * inv; xc[(4 * q + 1) * 128] = f.y * inv;
                xc[(4 * q + 2) * 128] = f.z * inv; xc[(4 * q + 3) * 128] = f.w * inv;
            }
        } else {
            #pragma unroll
            for (int q = 0; q < 10; q++) {
                float4 f = *(const float4*)(row + 48 + 4 * q);
                xc[(48 + 4 * q) * 128] = f.x * inv; xc[(49 + 4 * q) * 128] = f.y * inv;
                xc[(50 + 4 * q) * 128] = f.z * inv; xc[(51 + 4 * q) * 128] = f.w * inv;
            }
            xc[88 * 128] = row[88] * inv;
            xc[89 * 128] = row[89] * inv;
            xc[90 * 128] = row[90] * inv;
            #pragma unroll
            for (int k = 91; k < 96; k++) xc[k * 128] = 0.f;
        }
        __syncthreads();

        unsigned long long acc[32];
        #pragma unroll
        for (int i = 0; i < 32; i++) acc[i] = 0ull;
        MMA_BODY(ws, xs, acc, tx, ty)

        const float bj0 = bias_s[tx * 4], bj1 = bias_s[tx * 4 + 1];
        const float bj2 = bias_s[tx * 4 + 2], bj3 = bias_s[tx * 4 + 3];
        #pragma unroll
        for (int pr = 0; pr < 8; pr++) {
            int s0 = t * 128 + ty * 16 + 2 * pr;
            float c0[4], c1[4];
            upk(acc[pr],      c0[0], c1[0]);
            upk(acc[8 + pr],  c0[1], c1[1]);
            upk(acc[16 + pr], c0[2], c1[2]);
            upk(acc[24 + pr], c0[3], c1[3]);
            *(float4*)(g_Y + (size_t)s0 * 128 + tx * 4) =
                make_float4(c0[0] + bj0, c0[1] + bj1, c0[2] + bj2, c0[3] + bj3);
            *(float4*)(g_Y + (size_t)(s0 + 1) * 128 + tx * 4) =
                make_float4(c1[0] + bj0, c1[1] + bj1, c1[2] + bj2, c1[3] + bj3);
        }
        __syncthreads();
    }
}

// ---------------- K4: pass B — h[p] = W1*own[p] + Y[seg(p)], + stats ----------------
// smem: ws 12288 | xs 12288 | red 256 | sidx 128  = 99840 B
#define SMEM_B ((12288 + 12288 + 256 + 128) * 4)

__global__ __launch_bounds__(256, 2) void k_ptmm(
    const float* __restrict__ pts, const float* __restrict__ proj,
    const float* __restrict__ feat, const float* __restrict__ logi,
    const int* __restrict__ cidx, const void* __restrict__ fgm,
    const float* __restrict__ W, float* __restrict__ hout)
{
    extern __shared__ __align__(16) float smf[];
    float* ws = smf;
    float* xs = smf + 12288;
    float* red = smf + 24576;
    int* sidx_s = (int*)(smf + 24832);

    const int tid = threadIdx.x;
    const int tx = tid & 31, ty = tid >> 5;
    const int r = tid & 127, half = tid >> 7;
    const int fl = g_flags;

    for (int i = tid; i < 12288; i += 256) {
        int k = i >> 7, n = i & 127;
        ws[i] = (k < 91) ? W[n * DIN + k] : 0.f;
    }
    float s_sum[4], s_sq[4];
    #pragma unroll
    for (int j = 0; j < 4; j++) { s_sum[j] = 0.f; s_sq[j] = 0.f; }
    __syncthreads();

    for (int t = blockIdx.x; t < NT_B; t += GRID) {
        const int p = t * 128 + r;
        const bool ok = p < NPTS;
        float* xc = xs + r;
        if (half == 0) {
            if (ok) {
                #pragma unroll
                for (int q = 0; q < 12; q++) {
                    float4 f = *(const float4*)(feat + (size_t)p * 64 + 4 * q);
                    xc[(4 * q + 0) * 128] = f.x; xc[(4 * q + 1) * 128] = f.y;
                    xc[(4 * q + 2) * 128] = f.z; xc[(4 * q + 3) * 128] = f.w;
                }
                sidx_s[r] = cidx[p] * 2 + fg_of(fgm, p, fl);
            } else {
                #pragma unroll
                for (int k = 0; k < 48; k++) xc[k * 128] = 0.f;
                sidx_s[r] = 0;
            }
        } else {
            if (ok) {
                #pragma unroll
                for (int q = 0; q < 4; q++) {
                    float4 f = *(const float4*)(feat + (size_t)p * 64 + 48 + 4 * q);
                    xc[(48 + 4 * q) * 128] = f.x; xc[(49 + 4 * q) * 128] = f.y;
                    xc[(50 + 4 * q) * 128] = f.z; xc[(51 + 4 * q) * 128] = f.w;
                }
                #pragma unroll
                for (int q = 0; q < 5; q++) {
                    float4 f = *(const float4*)(logi + (size_t)p * 20 + 4 * q);
                    xc[(64 + 4 * q) * 128] = f.x; xc[(65 + 4 * q) * 128] = f.y;
                    xc[(66 + 4 * q) * 128] = f.z; xc[(67 + 4 * q) * 128] = f.w;
                }
                float4 f = *(const float4*)(pts + (size_t)p * 4);
                xc[84 * 128] = f.x; xc[85 * 128] = f.y; xc[86 * 128] = f.z; xc[87 * 128] = f.w;
                const float* pr = proj + (size_t)p * 3;
                xc[88 * 128] = pr[0]; xc[89 * 128] = pr[1]; xc[90 * 128] = pr[2];
            } else {
                #pragma unroll
                for (int k = 48; k < 91; k++) xc[k * 128] = 0.f;
            }
            #pragma unroll
            for (int k = 91; k < 96; k++) xc[k * 128] = 0.f;
        }
        __syncthreads();

        unsigned long long acc[32];
        #pragma unroll
        for (int i = 0; i < 32; i++) acc[i] = 0ull;
        MMA_BODY(ws, xs, acc, tx, ty)

        #pragma unroll
        for (int pr = 0; pr < 8; pr++) {
            int rl = ty * 16 + 2 * pr;
            int row0 = t * 128 + rl;
            int s0 = sidx_s[rl], s1 = sidx_s[rl + 1];
            float4 y0 = *(const float4*)(g_Y + (size_t)s0 * 128 + tx * 4);
            float4 y1 = *(const float4*)(g_Y + (size_t)s1 * 128 + tx * 4);
            float c0[4], c1[4];
            upk(acc[pr],      c0[0], c1[0]);
            upk(acc[8 + pr],  c0[1], c1[1]);
            upk(acc[16 + pr], c0[2], c1[2]);
            upk(acc[24 + pr], c0[3], c1[3]);
            c0[0] += y0.x; c0[1] += y0.y; c0[2] += y0.z; c0[3] += y0.w;
            c1[0] += y1.x; c1[1] += y1.y; c1[2] += y1.z; c1[3] += y1.w;
            if (row0 < NPTS) {
                #pragma unroll
                for (int j = 0; j < 4; j++) { s_sum[j] += c0[j]; s_sq[j] += c0[j] * c0[j]; }
                *(float4*)(hout + (size_t)row0 * 128 + tx * 4) =
                    make_float4(c0[0], c0[1], c0[2], c0[3]);
                if (row0 + 1 < NPTS) {
                    #pragma unroll
                    for (int j = 0; j < 4; j++) { s_sum[j] += c1[j]; s_sq[j] += c1[j] * c1[j]; }
                    *(float4*)(hout + (size_t)(row0 + 1) * 128 + tx * 4) =
                        make_float4(c1[0], c1[1], c1[2], c1[3]);
                }
            }
        }
        __syncthreads();
    }

    // per-CTA stats reduction
    if (tid < 256) red[tid] = 0.f;
    __syncthreads();
    #pragma unroll
    for (int j = 0; j < 4; j++) {
        atomicAdd(&red[tx * 4 + j], s_sum[j]);
        atomicAdd(&red[128 + tx * 4 + j], s_sq[j]);
    }
    __syncthreads();
    if (tid < 128) {
        atomicAdd(&g_sum[tid], red[tid]);
        atomicAdd(&g_sumsq[tid], red[128 + tid]);
    }
}

// ---------------- K5: BN coefficients ----------------
__global__ void k_bn(const float* __restrict__ gamma, const float* __restrict__ beta) {
    int c = threadIdx.x;
    float mu = g_sum[c] * (1.0f / NPTS);
    float var = g_sumsq[c] * (1.0f / NPTS) - mu * mu;
    float sc = gamma[c] * rsqrtf(var + 1e-5f);
    g_scale[c] = sc;
    g_shift[c] = beta[c] - mu * sc;
}

// ---------------- K6: normalize + LeakyReLU ----------------
__global__ void k_apply(float* __restrict__ out) {
    int64_t i0 = (int64_t)blockIdx.x * blockDim.x + threadIdx.x;
    int64_t st = (int64_t)gridDim.x * blockDim.x;
    float4* o4 = (float4*)out;
    for (int64_t i = i0; i < (int64_t)NPTS * 32; i += st) {
        float4 v = o4[i];
        int c = (int)(i & 31) * 4;
        float a0 = v.x * g_scale[c]     + g_shift[c];
        float a1 = v.y * g_scale[c + 1] + g_shift[c + 1];
        float a2 = v.z * g_scale[c + 2] + g_shift[c + 2];
        float a3 = v.w * g_scale[c + 3] + g_shift[c + 3];
        v.x = a0 >= 0.f ? a0 : 0.1f * a0;
        v.y = a1 >= 0.f ? a1 : 0.1f * a1;
        v.z = a2 >= 0.f ? a2 : 0.1f * a2;
        v.w = a3 >= 0.f ? a3 : 0.1f * a3;
        o4[i] = v;
    }
}

extern "C" void kernel_launch(void* const* d_in, const int* in_sizes, int n_in,
                              void* d_out, int out_size) {
    const float* pts  = (const float*)d_in[0];
    const float* proj = (const float*)d_in[1];
    const float* feat = (const float*)d_in[2];
    const float* logi = (const float*)d_in[3];
    const int*   cidx = (const int*)d_in[4];
    const void*  fgm  = d_in[5];
    const float* W    = (const float*)d_in[6];
    const float* b    = (const float*)d_in[7];
    const float* gamma= (const float*)d_in[8];
    const float* beta = (const float*)d_in[9];
    float* out = (float*)d_out;

    cudaFuncSetAttribute(k_segmm, cudaFuncAttributeMaxDynamicSharedMemorySize, SMEM_A);
    cudaFuncSetAttribute(k_ptmm, cudaFuncAttributeMaxDynamicSharedMemorySize, SMEM_B);

    k_zero<<<2048, 256>>>();
    k_detect<<<64, 256>>>((const unsigned int*)fgm);
    k_scatter<<<2048, 256>>>(pts, proj, feat, logi, cidx, fgm);
    k_segmm<<<GRID, 256, SMEM_A>>>(W, b);
    k_ptmm<<<GRID, 256, SMEM_B>>>(pts, proj, feat, logi, cidx, fgm, W, out);
    k_bn<<<1, 128>>>(gamma, beta);
    k_apply<<<2048, 256>>>(out);
}